// round 15
// baseline (speedup 1.0000x reference)
#include <cuda_runtime.h>
#include <cuda_bf16.h>
#include <cuda_fp16.h>
#include <cstdint>
#include <cstddef>

// out[8192,4096] = x[8192,4096] @ quantize(W)^T * scale + bias
#define MROWS 8192
#define KDIM  4096
#define NDIM  4096

constexpr int BM = 128, BN = 128, BK = 64;
constexpr int NST = 3;
constexpr int KTILES = KDIM / BK;                 // 64
constexpr int NTX = NDIM / BN;                    // 32
constexpr int TOTAL_TILES = (MROWS / BM) * NTX;   // 2048
constexpr int GRIDP = 296;                        // 148 SMs x 2 CTAs
constexpr int TILE_A = BM * BK * 2;               // 16KB
constexpr int TILE_B = BN * BK * 2;               // 16KB
constexpr int STAGE_BYTES = TILE_A + TILE_B;      // 32KB
constexpr int OFF_A = 0;
constexpr int OFF_B = TILE_A;
constexpr int SMEM_TOTAL = NST * STAGE_BYTES;     // 96KB -> 2 CTAs/SM

// ---------------- static scratch (allocations forbidden) ----------------
__device__ __align__(16) __half g_XF[(size_t)MROWS * KDIM];  // 64 MB fp16 x
__device__ __align__(16) __half g_Q [(size_t)NDIM  * KDIM];  // 32 MB fp16 ternary

// ---------------- helpers (sm_80-level PTX only) ----------------
__device__ __forceinline__ uint32_t smem_u32(const void* p) {
    uint32_t a;
    asm("{ .reg .u64 t; cvta.to.shared.u64 t, %1; cvt.u32.u64 %0, t; }" : "=r"(a) : "l"(p));
    return a;
}
__device__ __forceinline__ void cp16(uint32_t dst, const void* src) {
    asm volatile("cp.async.cg.shared.global [%0], [%1], 16;" :: "r"(dst), "l"(src));
}
__device__ __forceinline__ void cp_commit() {
    asm volatile("cp.async.commit_group;" ::: "memory");
}
__device__ __forceinline__ uint32_t swz128(uint32_t off) {   // SW128, 128B rows
    return off ^ ((off >> 3) & 0x70);
}
__device__ __forceinline__ void ldm_x4(uint32_t* r, uint32_t addr) {
    asm volatile("ldmatrix.sync.aligned.m8n8.x4.shared.b16 {%0,%1,%2,%3}, [%4];"
                 : "=r"(r[0]), "=r"(r[1]), "=r"(r[2]), "=r"(r[3]) : "r"(addr));
}
__device__ __forceinline__ void mma_fp16(float* c, const uint32_t* a, const uint32_t* b) {
    asm volatile(
        "mma.sync.aligned.m16n8k16.row.col.f32.f16.f16.f32 "
        "{%0,%1,%2,%3}, {%4,%5,%6,%7}, {%8,%9}, {%0,%1,%2,%3};"
        : "+f"(c[0]), "+f"(c[1]), "+f"(c[2]), "+f"(c[3])
        : "r"(a[0]), "r"(a[1]), "r"(a[2]), "r"(a[3]), "r"(b[0]), "r"(b[1]));
}
__device__ __forceinline__ uint32_t packh2(float a, float b) {
    __half2 h = __floats2half2_rn(a, b);
    return *reinterpret_cast<uint32_t*>(&h);
}

// ---------------- kernel 1: quantize W (W row cached in smem) + convert x ----------------
__global__ __launch_bounds__(256) void prep_kernel(const float* __restrict__ W,
                                                   const float* __restrict__ x) {
    const int tid = threadIdx.x;
    if (blockIdx.x < NDIM) {
        __shared__ float4 wrow[KDIM / 4];      // 16KB
        __shared__ float red[8];
        __shared__ float alphaS;
        const int row = blockIdx.x;
        const float4* w4 = reinterpret_cast<const float4*>(W + (size_t)row * KDIM);
        float s = 0.f;
        #pragma unroll 4
        for (int i = tid; i < KDIM / 4; i += 256) {
            float4 v = w4[i];
            wrow[i] = v;
            s += fabsf(v.x) + fabsf(v.y) + fabsf(v.z) + fabsf(v.w);
        }
        #pragma unroll
        for (int o = 16; o > 0; o >>= 1) s += __shfl_xor_sync(0xFFFFFFFFu, s, o);
        if ((tid & 31) == 0) red[tid >> 5] = s;
        __syncthreads();
        if (tid == 0) {
            float t = 0.f;
            #pragma unroll
            for (int i = 0; i < 8; i++) t += red[i];
            alphaS = t / (float)KDIM;
        }
        __syncthreads();
        const float alpha = alphaS;
        uint2* q2 = reinterpret_cast<uint2*>(g_Q + (size_t)row * KDIM);
        #pragma unroll 4
        for (int i = tid; i < KDIM / 4; i += 256) {
            float4 v = wrow[i];
            float q0 = (v.x > alpha) ? 1.f : ((v.x < -alpha) ? -1.f : 0.f);
            float q1 = (v.y > alpha) ? 1.f : ((v.y < -alpha) ? -1.f : 0.f);
            float q2v = (v.z > alpha) ? 1.f : ((v.z < -alpha) ? -1.f : 0.f);
            float q3 = (v.w > alpha) ? 1.f : ((v.w < -alpha) ? -1.f : 0.f);
            uint2 o; o.x = packh2(q0, q1); o.y = packh2(q2v, q3);
            q2[i] = o;
        }
    } else {
        const size_t n4 = (size_t)MROWS * KDIM / 4;
        const float4* x4 = reinterpret_cast<const float4*>(x);
        uint2* h4 = reinterpret_cast<uint2*>(g_XF);
        const size_t stride = (size_t)(gridDim.x - NDIM) * 256;
        for (size_t i = (size_t)(blockIdx.x - NDIM) * 256 + tid; i < n4; i += stride) {
            float4 v = x4[i];
            uint2 hh; hh.x = packh2(v.x, v.y); hh.y = packh2(v.z, v.w);
            h4[i] = hh;
        }
    }
}

#define ROWB ((size_t)KDIM * 2)

// ---------------- kernel 2: persistent flat-stream, 64x64 warp tiles, 2 CTAs/SM ----------------
__global__ __launch_bounds__(128, 2) void gemm_kernel(const float* __restrict__ scale,
                                                      const float* __restrict__ bias,
                                                      float* __restrict__ out) {
    extern __shared__ __align__(1024) char smem[];
    const uint32_t sb = smem_u32(smem);
    const int tid = threadIdx.x;
    const int wid = tid >> 5;
    const int lid = tid & 31;
    const int bid = blockIdx.x;

    const int warp_m = wid & 1;     // 2 warps along M: 64 rows each
    const int warp_n = wid >> 1;    // 2 warps along N: 64 cols each

    const int cnt = (TOTAL_TILES - 1 - bid) / GRIDP + 1;
    const int S = cnt * KTILES;     // total flat stages for this CTA

    // ---- per-thread copy mapping ----
    const int r0 = tid >> 3;            // 0..15
    const int ch = tid & 7;
    const uint32_t dOff = swz128((uint32_t)(r0 * 128 + ch * 16));  // row%8 invariant +16
    const char* xfB = reinterpret_cast<const char*>(g_XF) + (size_t)r0 * ROWB + (size_t)ch * 16;
    const char* qqB = reinterpret_cast<const char*>(g_Q)  + (size_t)r0 * ROWB + (size_t)ch * 16;

    // consumer tile state
    int T_cons = bid;
    // copy-cursor state (tracks the tile/kt of the NEXT stage to issue)
    int T_copy = bid;
    int copyKt = 0;
    const char* aCpC = xfB + (size_t)((T_copy >> 5) * BM) * ROWB;
    const char* bCpC = qqB + (size_t)((T_copy & 31) * BN) * ROWB;

    float acc[4][8][4];
    #pragma unroll
    for (int mi = 0; mi < 4; mi++)
        #pragma unroll
        for (int ni = 0; ni < 8; ni++)
            #pragma unroll
            for (int k = 0; k < 4; k++) acc[mi][ni][k] = 0.f;

    // ---- prologue: stages 0,1 in flight ----
    #pragma unroll
    for (int s = 0; s < 2; s++) {
        const uint32_t stg = sb + (uint32_t)s * STAGE_BYTES;
        #pragma unroll
        for (int i = 0; i < 8; i++)
            cp16(stg + OFF_A + dOff + (uint32_t)(i * 2048), aCpC + (size_t)i * 16 * ROWB);
        #pragma unroll
        for (int i = 0; i < 8; i++)
            cp16(stg + OFF_B + dOff + (uint32_t)(i * 2048), bCpC + (size_t)i * 16 * ROWB);
        cp_commit();
        aCpC += 128; bCpC += 128; copyKt++;
    }

    // ldmatrix lane address components
    const int lane15 = lid & 15;
    const int laneHiA = lid >> 4;
    const int rowBl = (lid & 7) + ((lid >> 4) & 1) * 8;
    const int chBl  = (lid >> 3) & 1;
    const uint32_t aAddrBase = (uint32_t)((warp_m * 64 + lane15) * 128 + laneHiA * 16);
    const uint32_t bAddrBase = (uint32_t)((warp_n * 64 + rowBl) * 128 + chBl * 16);

    uint32_t af[2][4][4];   // [buf][m16][regs]
    uint32_t bf[2][4][4];   // [buf][n16 quad][regs]

    // wait for stage 0, visibility, prefetch its k0 fragments
    asm volatile("cp.async.wait_group 1;" ::: "memory");
    __syncthreads();
    #pragma unroll
    for (int mi = 0; mi < 4; mi++)
        ldm_x4(af[0][mi], sb + OFF_A + swz128(aAddrBase + (uint32_t)(mi * 16 * 128)));
    #pragma unroll
    for (int nq = 0; nq < 4; nq++)
        ldm_x4(bf[0][nq], sb + OFF_B + swz128(bAddrBase + (uint32_t)(nq * 16 * 128)));

    // epilogue lane components
    const int qrow = lid >> 2;
    const int qcol = (lid & 3) * 2;

    int sIdx = 0;
    for (int g = 0; g < S; g++) {
        const uint32_t stage = sb + (uint32_t)sIdx * STAGE_BYTES;
        const uint32_t aS = stage + OFF_A;
        const uint32_t bS = stage + OFF_B;

        #pragma unroll
        for (int k16 = 0; k16 < 4; k16++) {
            const int cur = k16 & 1;
            const int nxt = cur ^ 1;

            if (k16 < 3) {
                // prefetch next k16 of current stage
                const uint32_t kOff = (uint32_t)((k16 + 1) * 32);
                #pragma unroll
                for (int mi = 0; mi < 4; mi++)
                    ldm_x4(af[nxt][mi],
                           aS + swz128(aAddrBase + kOff + (uint32_t)(mi * 16 * 128)));
                #pragma unroll
                for (int nq = 0; nq < 4; nq++)
                    ldm_x4(bf[nxt][nq],
                           bS + swz128(bAddrBase + kOff + (uint32_t)(nq * 16 * 128)));
            } else if (g + 1 < S) {
                // tail handoff: issue copies for stage g+2 (any tile), FIFO wait for g+1,
                // barrier, then prefetch stage g+1's k0 fragments.
                if (g + 2 < S) {
                    int sj = sIdx + 2; if (sj >= NST) sj -= NST;
                    const uint32_t stg = sb + (uint32_t)sj * STAGE_BYTES;
                    #pragma unroll
                    for (int i = 0; i < 8; i++)
                        cp16(stg + OFF_A + dOff + (uint32_t)(i * 2048),
                             aCpC + (size_t)i * 16 * ROWB);
                    #pragma unroll
                    for (int i = 0; i < 8; i++)
                        cp16(stg + OFF_B + dOff + (uint32_t)(i * 2048),
                             bCpC + (size_t)i * 16 * ROWB);
                    aCpC += 128; bCpC += 128;
                    if (++copyKt == KTILES) {        // cursor crosses tile boundary
                        copyKt = 0;
                        T_copy += GRIDP;
                        if (T_copy < TOTAL_TILES) {
                            aCpC = xfB + (size_t)((T_copy >> 5) * BM) * ROWB;
                            bCpC = qqB + (size_t)((T_copy & 31) * BN) * ROWB;
                        }
                    }
                }
                cp_commit();
                asm volatile("cp.async.wait_group 1;" ::: "memory");
                __syncthreads();
                int sn = sIdx + 1; if (sn >= NST) sn -= NST;
                const uint32_t nstg = sb + (uint32_t)sn * STAGE_BYTES;
                #pragma unroll
                for (int mi = 0; mi < 4; mi++)
                    ldm_x4(af[nxt][mi],
                           nstg + OFF_A + swz128(aAddrBase + (uint32_t)(mi * 16 * 128)));
                #pragma unroll
                for (int nq = 0; nq < 4; nq++)
                    ldm_x4(bf[nxt][nq],
                           nstg + OFF_B + swz128(bAddrBase + (uint32_t)(nq * 16 * 128)));
            }

            #pragma unroll
            for (int mi = 0; mi < 4; mi++)
                #pragma unroll
                for (int ni = 0; ni < 8; ni++)
                    mma_fp16(acc[mi][ni], af[cur][mi], &bf[cur][ni >> 1][(ni & 1) * 2]);
        }

        if (++sIdx == NST) sIdx = 0;

        if ((g & (KTILES - 1)) == KTILES - 1) {
            // tile complete: epilogue while next tile's copies/fragments are in flight
            const int mtile = T_cons >> 5, ntile = T_cons & 31;
            #pragma unroll
            for (int mi = 0; mi < 4; mi++) {
                #pragma unroll
                for (int ni = 0; ni < 8; ni++) {
                    const int gcol = ntile * BN + warp_n * 64 + ni * 8 + qcol;
                    const float2 sc = __ldg(reinterpret_cast<const float2*>(scale + gcol));
                    const float2 bi = __ldg(reinterpret_cast<const float2*>(bias + gcol));
                    const int grow0 = mtile * BM + warp_m * 64 + mi * 16 + qrow;
                    float2 v0, v1;
                    v0.x = acc[mi][ni][0] * sc.x + bi.x;
                    v0.y = acc[mi][ni][1] * sc.y + bi.y;
                    v1.x = acc[mi][ni][2] * sc.x + bi.x;
                    v1.y = acc[mi][ni][3] * sc.y + bi.y;
                    *reinterpret_cast<float2*>(out + (size_t)grow0 * NDIM + gcol) = v0;
                    *reinterpret_cast<float2*>(out + (size_t)(grow0 + 8) * NDIM + gcol) = v1;
                    acc[mi][ni][0] = 0.f; acc[mi][ni][1] = 0.f;
                    acc[mi][ni][2] = 0.f; acc[mi][ni][3] = 0.f;
                }
            }
            T_cons += GRIDP;
        }
    }
}

// ---------------- launch ----------------
extern "C" void kernel_launch(void* const* d_in, const int* in_sizes, int n_in,
                              void* d_out, int out_size) {
    const float* x      = (const float*)d_in[0];
    const float* weight = (const float*)d_in[1];
    const float* scale  = (const float*)d_in[2];
    const float* bias   = (const float*)d_in[3];
    float* out = (float*)d_out;

    prep_kernel<<<NDIM + 8192, 256>>>(weight, x);

    cudaFuncSetAttribute(gemm_kernel, cudaFuncAttributeMaxDynamicSharedMemorySize, SMEM_TOTAL);
    gemm_kernel<<<GRIDP, 128, SMEM_TOTAL>>>(scale, bias, out);
}

// round 16
// speedup vs baseline: 1.1689x; 1.1689x over previous
#include <cuda_runtime.h>
#include <cuda_bf16.h>
#include <cuda_fp16.h>
#include <cstdint>
#include <cstddef>

// out[8192,4096] = x[8192,4096] @ quantize(W)^T * scale + bias
#define MROWS 8192
#define KDIM  4096
#define NDIM  4096

constexpr int BM = 128, BN = 128, BK = 64;
constexpr int NST = 3;
constexpr int KTILES = KDIM / BK;                 // 64
constexpr int TILE_A = BM * BK * 2;               // 16KB
constexpr int TILE_B = BN * BK * 2;               // 16KB
constexpr int STAGE_BYTES = TILE_A + TILE_B;      // 32KB
constexpr int OFF_A = 0;
constexpr int OFF_B = TILE_A;
constexpr int SMEM_TOTAL = NST * STAGE_BYTES;     // 96KB -> 2 CTAs/SM

// ---------------- static scratch (allocations forbidden) ----------------
__device__ __align__(16) __half g_XF[(size_t)MROWS * KDIM];  // 64 MB fp16 x
__device__ __align__(16) __half g_Q [(size_t)NDIM  * KDIM];  // 32 MB fp16 ternary

// ---------------- helpers (sm_80-level PTX only) ----------------
__device__ __forceinline__ uint32_t smem_u32(const void* p) {
    uint32_t a;
    asm("{ .reg .u64 t; cvta.to.shared.u64 t, %1; cvt.u32.u64 %0, t; }" : "=r"(a) : "l"(p));
    return a;
}
__device__ __forceinline__ void cp16(uint32_t dst, const void* src) {
    asm volatile("cp.async.cg.shared.global [%0], [%1], 16;" :: "r"(dst), "l"(src));
}
__device__ __forceinline__ void cp_commit() {
    asm volatile("cp.async.commit_group;" ::: "memory");
}
__device__ __forceinline__ uint32_t swz128(uint32_t off) {   // SW128, 128B rows
    return off ^ ((off >> 3) & 0x70);
}
__device__ __forceinline__ void ldm_x4(uint32_t* r, uint32_t addr) {
    asm volatile("ldmatrix.sync.aligned.m8n8.x4.shared.b16 {%0,%1,%2,%3}, [%4];"
                 : "=r"(r[0]), "=r"(r[1]), "=r"(r[2]), "=r"(r[3]) : "r"(addr));
}
__device__ __forceinline__ void mma_fp16(float* c, const uint32_t* a, const uint32_t* b) {
    asm volatile(
        "mma.sync.aligned.m16n8k16.row.col.f32.f16.f16.f32 "
        "{%0,%1,%2,%3}, {%4,%5,%6,%7}, {%8,%9}, {%0,%1,%2,%3};"
        : "+f"(c[0]), "+f"(c[1]), "+f"(c[2]), "+f"(c[3])
        : "r"(a[0]), "r"(a[1]), "r"(a[2]), "r"(a[3]), "r"(b[0]), "r"(b[1]));
}
__device__ __forceinline__ uint32_t packh2(float a, float b) {
    __half2 h = __floats2half2_rn(a, b);
    return *reinterpret_cast<uint32_t*>(&h);
}

// ---------------- kernel 1: quantize W (W row cached in smem) + convert x ----------------
__global__ __launch_bounds__(256) void prep_kernel(const float* __restrict__ W,
                                                   const float* __restrict__ x) {
    const int tid = threadIdx.x;
    if (blockIdx.x < NDIM) {
        __shared__ float4 wrow[KDIM / 4];      // 16KB
        __shared__ float red[8];
        __shared__ float alphaS;
        const int row = blockIdx.x;
        const float4* w4 = reinterpret_cast<const float4*>(W + (size_t)row * KDIM);
        float s = 0.f;
        #pragma unroll 4
        for (int i = tid; i < KDIM / 4; i += 256) {
            float4 v = w4[i];
            wrow[i] = v;
            s += fabsf(v.x) + fabsf(v.y) + fabsf(v.z) + fabsf(v.w);
        }
        #pragma unroll
        for (int o = 16; o > 0; o >>= 1) s += __shfl_xor_sync(0xFFFFFFFFu, s, o);
        if ((tid & 31) == 0) red[tid >> 5] = s;
        __syncthreads();
        if (tid == 0) {
            float t = 0.f;
            #pragma unroll
            for (int i = 0; i < 8; i++) t += red[i];
            alphaS = t / (float)KDIM;
        }
        __syncthreads();
        const float alpha = alphaS;
        uint2* q2 = reinterpret_cast<uint2*>(g_Q + (size_t)row * KDIM);
        #pragma unroll 4
        for (int i = tid; i < KDIM / 4; i += 256) {
            float4 v = wrow[i];
            float q0 = (v.x > alpha) ? 1.f : ((v.x < -alpha) ? -1.f : 0.f);
            float q1 = (v.y > alpha) ? 1.f : ((v.y < -alpha) ? -1.f : 0.f);
            float q2v = (v.z > alpha) ? 1.f : ((v.z < -alpha) ? -1.f : 0.f);
            float q3 = (v.w > alpha) ? 1.f : ((v.w < -alpha) ? -1.f : 0.f);
            uint2 o; o.x = packh2(q0, q1); o.y = packh2(q2v, q3);
            q2[i] = o;
        }
    } else {
        const size_t n4 = (size_t)MROWS * KDIM / 4;
        const float4* x4 = reinterpret_cast<const float4*>(x);
        uint2* h4 = reinterpret_cast<uint2*>(g_XF);
        const size_t stride = (size_t)(gridDim.x - NDIM) * 256;
        for (size_t i = (size_t)(blockIdx.x - NDIM) * 256 + tid; i < n4; i += stride) {
            float4 v = x4[i];
            uint2 hh; hh.x = packh2(v.x, v.y); hh.y = packh2(v.z, v.w);
            h4[i] = hh;
        }
    }
}

#define ROWB ((size_t)KDIM * 2)

// ---------------- kernel 2: 128-thread CTA, 64x64 warp tiles, spread-copy pipeline ----------------
__global__ __launch_bounds__(128, 2) void gemm_kernel(const float* __restrict__ scale,
                                                      const float* __restrict__ bias,
                                                      float* __restrict__ out) {
    extern __shared__ __align__(1024) char smem[];
    const uint32_t sb = smem_u32(smem);
    const int tid = threadIdx.x;
    const int wid = tid >> 5;
    const int lid = tid & 31;
    const int ntile = blockIdx.x;   // 32
    const int mtile = blockIdx.y;   // 64

    const int warp_m = wid & 1;     // 2 warps along M: 64 rows each
    const int warp_n = wid >> 1;    // 2 warps along N: 64 cols each

    // ---- per-thread copy mapping: 128 threads; A/B 8 chunks each; rows advance +16 ----
    const int r0 = tid >> 3;            // 0..15
    const int ch = tid & 7;
    const uint32_t dOff = swz128((uint32_t)(r0 * 128 + ch * 16));  // row%8 invariant +16
    const char* aCp = reinterpret_cast<const char*>(g_XF) +
                      (size_t)(mtile * BM + r0) * ROWB + (size_t)ch * 16;
    const char* bCp = reinterpret_cast<const char*>(g_Q) +
                      (size_t)(ntile * BN + r0) * ROWB + (size_t)ch * 16;

    float acc[4][8][4];
    #pragma unroll
    for (int mi = 0; mi < 4; mi++)
        #pragma unroll
        for (int ni = 0; ni < 8; ni++)
            #pragma unroll
            for (int k = 0; k < 4; k++) acc[mi][ni][k] = 0.f;

    // ---- prologue: stages 0,1 in flight ----
    #pragma unroll
    for (int s = 0; s < 2; s++) {
        const uint32_t stg = sb + (uint32_t)s * STAGE_BYTES;
        #pragma unroll
        for (int i = 0; i < 8; i++)
            cp16(stg + OFF_A + dOff + (uint32_t)(i * 2048),
                 aCp + (size_t)s * 128 + (size_t)i * 16 * ROWB);
        #pragma unroll
        for (int i = 0; i < 8; i++)
            cp16(stg + OFF_B + dOff + (uint32_t)(i * 2048),
                 bCp + (size_t)s * 128 + (size_t)i * 16 * ROWB);
        cp_commit();
    }
    aCp += 256; bCp += 256;   // next stage to issue = kt+2

    // ldmatrix lane address components
    const int lane15 = lid & 15;
    const int laneHiA = lid >> 4;
    const int rowBl = (lid & 7) + ((lid >> 4) & 1) * 8;
    const int chBl  = (lid >> 3) & 1;
    const uint32_t aAddrBase = (uint32_t)((warp_m * 64 + lane15) * 128 + laneHiA * 16);
    const uint32_t bAddrBase = (uint32_t)((warp_n * 64 + rowBl) * 128 + chBl * 16);

    uint32_t af[2][4][4];   // [buf][m16][regs]
    uint32_t bf[2][4][4];   // [buf][n16 quad][regs]

    // wait for stage 0 (pending {0,1} -> <=1 means 0 done), visibility, prefetch its k0
    asm volatile("cp.async.wait_group 1;" ::: "memory");
    __syncthreads();
    #pragma unroll
    for (int mi = 0; mi < 4; mi++)
        ldm_x4(af[0][mi], sb + OFF_A + swz128(aAddrBase + (uint32_t)(mi * 16 * 128)));
    #pragma unroll
    for (int nq = 0; nq < 4; nq++)
        ldm_x4(bf[0][nq], sb + OFF_B + swz128(bAddrBase + (uint32_t)(nq * 16 * 128)));

    int sIdx = 0;
    for (int kt = 0; kt < KTILES; kt++) {
        const uint32_t stage = sb + (uint32_t)sIdx * STAGE_BYTES;
        const uint32_t aS = stage + OFF_A;
        const uint32_t bS = stage + OFF_B;

        // destination buffer for stage kt+2 (freed: last read in stage kt-1)
        int sj = sIdx + 2; if (sj >= NST) sj -= NST;
        const uint32_t cstg = sb + (uint32_t)sj * STAGE_BYTES;
        const bool doCopy = (kt + 2 < KTILES);

        #pragma unroll
        for (int k16 = 0; k16 < 4; k16++) {
            const int cur = k16 & 1;
            const int nxt = cur ^ 1;

            // spread cp.async issue for stage kt+2 across k16 = 0,1,2
            if (doCopy) {
                if (k16 == 0) {
                    #pragma unroll
                    for (int i = 0; i < 5; i++)
                        cp16(cstg + OFF_A + dOff + (uint32_t)(i * 2048),
                             aCp + (size_t)i * 16 * ROWB);
                } else if (k16 == 1) {
                    #pragma unroll
                    for (int i = 5; i < 8; i++)
                        cp16(cstg + OFF_A + dOff + (uint32_t)(i * 2048),
                             aCp + (size_t)i * 16 * ROWB);
                    #pragma unroll
                    for (int i = 0; i < 3; i++)
                        cp16(cstg + OFF_B + dOff + (uint32_t)(i * 2048),
                             bCp + (size_t)i * 16 * ROWB);
                } else if (k16 == 2) {
                    #pragma unroll
                    for (int i = 3; i < 8; i++)
                        cp16(cstg + OFF_B + dOff + (uint32_t)(i * 2048),
                             bCp + (size_t)i * 16 * ROWB);
                }
            }

            if (k16 < 3) {
                // prefetch next k16 of current stage
                const uint32_t kOff = (uint32_t)((k16 + 1) * 32);
                #pragma unroll
                for (int mi = 0; mi < 4; mi++)
                    ldm_x4(af[nxt][mi],
                           aS + swz128(aAddrBase + kOff + (uint32_t)(mi * 16 * 128)));
                #pragma unroll
                for (int nq = 0; nq < 4; nq++)
                    ldm_x4(bf[nxt][nq],
                           bS + swz128(bAddrBase + kOff + (uint32_t)(nq * 16 * 128)));
            } else if (kt + 1 < KTILES) {
                // tail handoff: commit this stage's copies -> FIFO wait for kt+1 ->
                // barrier -> prefetch kt+1's k0 fragments.
                cp_commit();
                asm volatile("cp.async.wait_group 1;" ::: "memory");
                __syncthreads();
                int sn = sIdx + 1; if (sn >= NST) sn -= NST;
                const uint32_t nstg = sb + (uint32_t)sn * STAGE_BYTES;
                #pragma unroll
                for (int mi = 0; mi < 4; mi++)
                    ldm_x4(af[nxt][mi],
                           nstg + OFF_A + swz128(aAddrBase + (uint32_t)(mi * 16 * 128)));
                #pragma unroll
                for (int nq = 0; nq < 4; nq++)
                    ldm_x4(bf[nxt][nq],
                           nstg + OFF_B + swz128(bAddrBase + (uint32_t)(nq * 16 * 128)));
            }

            #pragma unroll
            for (int mi = 0; mi < 4; mi++)
                #pragma unroll
                for (int ni = 0; ni < 8; ni++)
                    mma_fp16(acc[mi][ni], af[cur][mi], &bf[cur][ni >> 1][(ni & 1) * 2]);
        }

        if (doCopy) { aCp += 128; bCp += 128; }
        if (++sIdx == NST) sIdx = 0;
    }

    // epilogue: scale/bias via L2-hot __ldg + direct float2 stores
    const int qrow = lid >> 2;
    const int qcol = (lid & 3) * 2;
    #pragma unroll
    for (int mi = 0; mi < 4; mi++) {
        #pragma unroll
        for (int ni = 0; ni < 8; ni++) {
            const int gcol = ntile * BN + warp_n * 64 + ni * 8 + qcol;
            const float2 sc = __ldg(reinterpret_cast<const float2*>(scale + gcol));
            const float2 bi = __ldg(reinterpret_cast<const float2*>(bias + gcol));
            const int grow0 = mtile * BM + warp_m * 64 + mi * 16 + qrow;
            float2 v0, v1;
            v0.x = acc[mi][ni][0] * sc.x + bi.x;
            v0.y = acc[mi][ni][1] * sc.y + bi.y;
            v1.x = acc[mi][ni][2] * sc.x + bi.x;
            v1.y = acc[mi][ni][3] * sc.y + bi.y;
            *reinterpret_cast<float2*>(out + (size_t)grow0 * NDIM + gcol) = v0;
            *reinterpret_cast<float2*>(out + (size_t)(grow0 + 8) * NDIM + gcol) = v1;
        }
    }
}

// ---------------- launch ----------------
extern "C" void kernel_launch(void* const* d_in, const int* in_sizes, int n_in,
                              void* d_out, int out_size) {
    const float* x      = (const float*)d_in[0];
    const float* weight = (const float*)d_in[1];
    const float* scale  = (const float*)d_in[2];
    const float* bias   = (const float*)d_in[3];
    float* out = (float*)d_out;

    prep_kernel<<<NDIM + 8192, 256>>>(weight, x);

    cudaFuncSetAttribute(gemm_kernel, cudaFuncAttributeMaxDynamicSharedMemorySize, SMEM_TOTAL);
    dim3 grid(NDIM / BN, MROWS / BM);   // 32 x 64
    gemm_kernel<<<grid, 128, SMEM_TOTAL>>>(scale, bias, out);
}

// round 17
// speedup vs baseline: 1.2059x; 1.0317x over previous
#include <cuda_runtime.h>
#include <cuda_bf16.h>
#include <cuda_fp16.h>
#include <cstdint>
#include <cstddef>

// out[8192,4096] = x[8192,4096] @ quantize(W)^T * scale + bias
#define MROWS 8192
#define KDIM  4096
#define NDIM  4096

constexpr int BM = 128, BN = 128, BK = 64;
constexpr int NST = 3;
constexpr int KTILES = KDIM / BK;                 // 64
constexpr int TILE_A = BM * BK * 2;               // 16KB
constexpr int TILE_B = BN * BK * 2;               // 16KB
constexpr int STAGE_BYTES = TILE_A + TILE_B;      // 32KB
constexpr int OFF_A = 0;
constexpr int OFF_B = TILE_A;
constexpr int SMEM_TOTAL = NST * STAGE_BYTES;     // 96KB -> 2 CTAs/SM

// ---------------- static scratch (allocations forbidden) ----------------
__device__ __align__(16) __half g_XF[(size_t)MROWS * KDIM];  // 64 MB fp16 x
__device__ __align__(16) __half g_Q [(size_t)NDIM  * KDIM];  // 32 MB fp16 ternary

// ---------------- helpers (sm_80-level PTX only) ----------------
__device__ __forceinline__ uint32_t smem_u32(const void* p) {
    uint32_t a;
    asm("{ .reg .u64 t; cvta.to.shared.u64 t, %1; cvt.u32.u64 %0, t; }" : "=r"(a) : "l"(p));
    return a;
}
__device__ __forceinline__ void cp16(uint32_t dst, const void* src) {
    asm volatile("cp.async.cg.shared.global [%0], [%1], 16;" :: "r"(dst), "l"(src));
}
__device__ __forceinline__ void cp_commit() {
    asm volatile("cp.async.commit_group;" ::: "memory");
}
__device__ __forceinline__ uint32_t swz128(uint32_t off) {   // SW128, 128B rows
    return off ^ ((off >> 3) & 0x70);
}
__device__ __forceinline__ void ldm_x4(uint32_t* r, uint32_t addr) {
    asm volatile("ldmatrix.sync.aligned.m8n8.x4.shared.b16 {%0,%1,%2,%3}, [%4];"
                 : "=r"(r[0]), "=r"(r[1]), "=r"(r[2]), "=r"(r[3]) : "r"(addr));
}
__device__ __forceinline__ void mma_fp16(float* c, const uint32_t* a, const uint32_t* b) {
    asm volatile(
        "mma.sync.aligned.m16n8k16.row.col.f32.f16.f16.f32 "
        "{%0,%1,%2,%3}, {%4,%5,%6,%7}, {%8,%9}, {%0,%1,%2,%3};"
        : "+f"(c[0]), "+f"(c[1]), "+f"(c[2]), "+f"(c[3])
        : "r"(a[0]), "r"(a[1]), "r"(a[2]), "r"(a[3]), "r"(b[0]), "r"(b[1]));
}
__device__ __forceinline__ uint32_t packh2(float a, float b) {
    __half2 h = __floats2half2_rn(a, b);
    return *reinterpret_cast<uint32_t*>(&h);
}

// ---------------- kernel 1: quantize W + convert x, streaming cache hints ----------------
__global__ __launch_bounds__(256) void prep_kernel(const float* __restrict__ W,
                                                   const float* __restrict__ x) {
    const int tid = threadIdx.x;
    if (blockIdx.x < NDIM) {
        __shared__ float4 wrow[KDIM / 4];      // 16KB
        __shared__ float red[8];
        __shared__ float alphaS;
        const int row = blockIdx.x;
        const float4* w4 = reinterpret_cast<const float4*>(W + (size_t)row * KDIM);
        float s = 0.f;
        #pragma unroll 4
        for (int i = tid; i < KDIM / 4; i += 256) {
            float4 v = __ldcs(w4 + i);          // streaming read, no L2 retention
            wrow[i] = v;
            s += fabsf(v.x) + fabsf(v.y) + fabsf(v.z) + fabsf(v.w);
        }
        #pragma unroll
        for (int o = 16; o > 0; o >>= 1) s += __shfl_xor_sync(0xFFFFFFFFu, s, o);
        if ((tid & 31) == 0) red[tid >> 5] = s;
        __syncthreads();
        if (tid == 0) {
            float t = 0.f;
            #pragma unroll
            for (int i = 0; i < 8; i++) t += red[i];
            alphaS = t / (float)KDIM;
        }
        __syncthreads();
        const float alpha = alphaS;
        uint2* q2 = reinterpret_cast<uint2*>(g_Q + (size_t)row * KDIM);
        #pragma unroll 4
        for (int i = tid; i < KDIM / 4; i += 256) {
            float4 v = wrow[i];
            float q0 = (v.x > alpha) ? 1.f : ((v.x < -alpha) ? -1.f : 0.f);
            float q1 = (v.y > alpha) ? 1.f : ((v.y < -alpha) ? -1.f : 0.f);
            float q2v = (v.z > alpha) ? 1.f : ((v.z < -alpha) ? -1.f : 0.f);
            float q3 = (v.w > alpha) ? 1.f : ((v.w < -alpha) ? -1.f : 0.f);
            uint2 o; o.x = packh2(q0, q1); o.y = packh2(q2v, q3);
            __stcs(q2 + i, o);                  // streaming write
        }
    } else {
        // convert x fp32 -> fp16, 2x float4 per iteration for MLP, streaming hints
        const size_t n8 = (size_t)MROWS * KDIM / 8;
        const float4* x4 = reinterpret_cast<const float4*>(x);
        uint2* h4 = reinterpret_cast<uint2*>(g_XF);
        const size_t stride = (size_t)(gridDim.x - NDIM) * 256;
        for (size_t j = (size_t)(blockIdx.x - NDIM) * 256 + tid; j < n8; j += stride) {
            const size_t i = j * 2;
            float4 v0 = __ldcs(x4 + i);
            float4 v1 = __ldcs(x4 + i + 1);
            uint2 h0; h0.x = packh2(v0.x, v0.y); h0.y = packh2(v0.z, v0.w);
            uint2 h1; h1.x = packh2(v1.x, v1.y); h1.y = packh2(v1.z, v1.w);
            __stcs(h4 + i, h0);
            __stcs(h4 + i + 1, h1);
        }
    }
}

#define ROWB ((size_t)KDIM * 2)

// ---------------- kernel 2: 128-thread CTA, 64x64 warp tiles, tail-handoff (R14) ----------------
__global__ __launch_bounds__(128, 2) void gemm_kernel(const float* __restrict__ scale,
                                                      const float* __restrict__ bias,
                                                      float* __restrict__ out) {
    extern __shared__ __align__(1024) char smem[];
    const uint32_t sb = smem_u32(smem);
    const int tid = threadIdx.x;
    const int wid = tid >> 5;
    const int lid = tid & 31;
    const int ntile = blockIdx.x;   // 32
    const int mtile = blockIdx.y;   // 64

    const int warp_m = wid & 1;     // 2 warps along M: 64 rows each
    const int warp_n = wid >> 1;    // 2 warps along N: 64 cols each

    // ---- per-thread copy mapping: 128 threads; A/B 8 chunks each; rows advance +16 ----
    const int r0 = tid >> 3;            // 0..15
    const int ch = tid & 7;
    const uint32_t dOff = swz128((uint32_t)(r0 * 128 + ch * 16));  // row%8 invariant +16
    const char* aCp = reinterpret_cast<const char*>(g_XF) +
                      (size_t)(mtile * BM + r0) * ROWB + (size_t)ch * 16;
    const char* bCp = reinterpret_cast<const char*>(g_Q) +
                      (size_t)(ntile * BN + r0) * ROWB + (size_t)ch * 16;

    float acc[4][8][4];
    #pragma unroll
    for (int mi = 0; mi < 4; mi++)
        #pragma unroll
        for (int ni = 0; ni < 8; ni++)
            #pragma unroll
            for (int k = 0; k < 4; k++) acc[mi][ni][k] = 0.f;

    // ---- prologue: stages 0,1 in flight ----
    #pragma unroll
    for (int s = 0; s < 2; s++) {
        const uint32_t stg = sb + (uint32_t)s * STAGE_BYTES;
        #pragma unroll
        for (int i = 0; i < 8; i++)
            cp16(stg + OFF_A + dOff + (uint32_t)(i * 2048),
                 aCp + (size_t)s * 128 + (size_t)i * 16 * ROWB);
        #pragma unroll
        for (int i = 0; i < 8; i++)
            cp16(stg + OFF_B + dOff + (uint32_t)(i * 2048),
                 bCp + (size_t)s * 128 + (size_t)i * 16 * ROWB);
        cp_commit();
    }
    aCp += 256; bCp += 256;   // next stage to issue = kt+2

    // ldmatrix lane address components
    const int lane15 = lid & 15;
    const int laneHiA = lid >> 4;
    const int rowBl = (lid & 7) + ((lid >> 4) & 1) * 8;
    const int chBl  = (lid >> 3) & 1;
    const uint32_t aAddrBase = (uint32_t)((warp_m * 64 + lane15) * 128 + laneHiA * 16);
    const uint32_t bAddrBase = (uint32_t)((warp_n * 64 + rowBl) * 128 + chBl * 16);

    uint32_t af[2][4][4];   // [buf][m16][regs]
    uint32_t bf[2][4][4];   // [buf][n16 quad][regs]

    // wait for stage 0 (pending {0,1} -> <=1 means 0 done), visibility, prefetch its k0
    asm volatile("cp.async.wait_group 1;" ::: "memory");
    __syncthreads();
    #pragma unroll
    for (int mi = 0; mi < 4; mi++)
        ldm_x4(af[0][mi], sb + OFF_A + swz128(aAddrBase + (uint32_t)(mi * 16 * 128)));
    #pragma unroll
    for (int nq = 0; nq < 4; nq++)
        ldm_x4(bf[0][nq], sb + OFF_B + swz128(bAddrBase + (uint32_t)(nq * 16 * 128)));

    int sIdx = 0;
    for (int kt = 0; kt < KTILES; kt++) {
        const uint32_t stage = sb + (uint32_t)sIdx * STAGE_BYTES;
        const uint32_t aS = stage + OFF_A;
        const uint32_t bS = stage + OFF_B;

        #pragma unroll
        for (int k16 = 0; k16 < 4; k16++) {
            const int cur = k16 & 1;
            const int nxt = cur ^ 1;

            if (k16 < 3) {
                // prefetch next k16 of current stage
                const uint32_t kOff = (uint32_t)((k16 + 1) * 32);
                #pragma unroll
                for (int mi = 0; mi < 4; mi++)
                    ldm_x4(af[nxt][mi],
                           aS + swz128(aAddrBase + kOff + (uint32_t)(mi * 16 * 128)));
                #pragma unroll
                for (int nq = 0; nq < 4; nq++)
                    ldm_x4(bf[nxt][nq],
                           bS + swz128(bAddrBase + kOff + (uint32_t)(nq * 16 * 128)));
            } else if (kt + 1 < KTILES) {
                // tail handoff: copies for kt+2 -> commit -> FIFO wait for kt+1 -> barrier
                // -> prefetch kt+1's k0 fragments. Buffer (sIdx+2)%3 was last read in
                // stage kt-1 (all warps past that stage's barrier) -> safe to refill.
                if (kt + 2 < KTILES) {
                    int sj = sIdx + 2; if (sj >= NST) sj -= NST;
                    const uint32_t stg = sb + (uint32_t)sj * STAGE_BYTES;
                    #pragma unroll
                    for (int i = 0; i < 8; i++)
                        cp16(stg + OFF_A + dOff + (uint32_t)(i * 2048),
                             aCp + (size_t)i * 16 * ROWB);
                    #pragma unroll
                    for (int i = 0; i < 8; i++)
                        cp16(stg + OFF_B + dOff + (uint32_t)(i * 2048),
                             bCp + (size_t)i * 16 * ROWB);
                    aCp += 128; bCp += 128;
                }
                cp_commit();
                asm volatile("cp.async.wait_group 1;" ::: "memory");
                __syncthreads();
                int sn = sIdx + 1; if (sn >= NST) sn -= NST;
                const uint32_t nstg = sb + (uint32_t)sn * STAGE_BYTES;
                #pragma unroll
                for (int mi = 0; mi < 4; mi++)
                    ldm_x4(af[nxt][mi],
                           nstg + OFF_A + swz128(aAddrBase + (uint32_t)(mi * 16 * 128)));
                #pragma unroll
                for (int nq = 0; nq < 4; nq++)
                    ldm_x4(bf[nxt][nq],
                           nstg + OFF_B + swz128(bAddrBase + (uint32_t)(nq * 16 * 128)));
            }

            #pragma unroll
            for (int mi = 0; mi < 4; mi++)
                #pragma unroll
                for (int ni = 0; ni < 8; ni++)
                    mma_fp16(acc[mi][ni], af[cur][mi], &bf[cur][ni >> 1][(ni & 1) * 2]);
        }

        if (++sIdx == NST) sIdx = 0;
    }

    // epilogue: scale/bias via L2-hot __ldg + direct float2 stores
    const int qrow = lid >> 2;
    const int qcol = (lid & 3) * 2;
    #pragma unroll
    for (int mi = 0; mi < 4; mi++) {
        #pragma unroll
        for (int ni = 0; ni < 8; ni++) {
            const int gcol = ntile * BN + warp_n * 64 + ni * 8 + qcol;
            const float2 sc = __ldg(reinterpret_cast<const float2*>(scale + gcol));
            const float2 bi = __ldg(reinterpret_cast<const float2*>(bias + gcol));
            const int grow0 = mtile * BM + warp_m * 64 + mi * 16 + qrow;
            float2 v0, v1;
            v0.x = acc[mi][ni][0] * sc.x + bi.x;
            v0.y = acc[mi][ni][1] * sc.y + bi.y;
            v1.x = acc[mi][ni][2] * sc.x + bi.x;
            v1.y = acc[mi][ni][3] * sc.y + bi.y;
            *reinterpret_cast<float2*>(out + (size_t)grow0 * NDIM + gcol) = v0;
            *reinterpret_cast<float2*>(out + (size_t)(grow0 + 8) * NDIM + gcol) = v1;
        }
    }
}

// ---------------- launch ----------------
extern "C" void kernel_launch(void* const* d_in, const int* in_sizes, int n_in,
                              void* d_out, int out_size) {
    const float* x      = (const float*)d_in[0];
    const float* weight = (const float*)d_in[1];
    const float* scale  = (const float*)d_in[2];
    const float* bias   = (const float*)d_in[3];
    float* out = (float*)d_out;

    prep_kernel<<<NDIM + 8192, 256>>>(weight, x);

    cudaFuncSetAttribute(gemm_kernel, cudaFuncAttributeMaxDynamicSharedMemorySize, SMEM_TOTAL);
    dim3 grid(NDIM / BN, MROWS / BM);   // 32 x 64
    gemm_kernel<<<grid, 128, SMEM_TOTAL>>>(scale, bias, out);
}